// round 9
// baseline (speedup 1.0000x reference)
#include <cuda_runtime.h>

// DepthLoss3D: 408 blocks (48 diag + 360 pairs), one unit per block.
// NO global bitonic sort. Each warp sorts its 32 values in registers,
// publishes 8 sorted runs + run-prefix-sums; each thread gets global rank
// and global prefix via 7 small binary searches (stable tie-break).
// Queries (proven R6 closed form) run against the scattered sorted array:
//   f(x) = max(x-ds, 0.2ds-x, 0) - 0.2ds*[x<0],  x = p - pb, ds > 0
//   sum_j f = n1*k1 - P[n1] + (T - P[n2]) - (256-n2)*k2 - 0.2ds*(256-n3)
// Diagonal: sum_t v_t * (2*rank_t - 255).

#define N_ELEM 4096

__device__ __forceinline__ int elem_index(int c, int g, int m) {
    if (c == 0)      return (g << 8) + m;
    else if (c == 1) return ((m >> 4) << 8) + (g << 4) + (m & 15);
    else             return (m << 4) + g;
}

__global__ void __launch_bounds__(256) depthloss_rank(
    const float* __restrict__ pred,   // [4096,3]
    const float* __restrict__ spac,   // [3]
    float* __restrict__ out)          // [3]
{
    __shared__ float srun[8 * 33];    // 8 sorted runs, padded
    __shared__ float spre[8 * 34];    // per-run inclusive prefix (index 0..32)
    __shared__ float sv[256];         // merged sorted values (by rank)
    __shared__ float sp[257];         // merged prefix sums
    __shared__ float red[8];

    const int t    = threadIdx.x;
    const int lane = t & 31;
    const int wid  = t >> 5;
    const int bx   = blockIdx.x;

    // Task decode: bx < 48 -> diagonal (c,g); else pair (c, a>b).
    int c, a, b;
    bool diag;
    if (bx < 48) {
        diag = true;
        c = bx >> 4;
        a = b = bx & 15;
    } else {
        diag = false;
        const int idx = bx - 48;
        c = idx / 120;
        const int pq = idx - c * 120;
        a = 1;
        while ((a + 1) * a / 2 <= pq) ++a;
        b = pq - a * (a - 1) / 2;
    }

    float v = pred[elem_index(c, b, t) * 3 + c];
    float p = diag ? 0.0f : pred[elem_index(c, a, t) * 3 + c];

    // ---- Warp-local bitonic sort (ascending by lane), 15 SHFL stages. ----
#define WSH(J, UP) do {                                             \
        const float o_ = __shfl_xor_sync(0xffffffffu, v, (J));      \
        const bool mn_ = (((lane & (J)) == 0) == (UP));             \
        v = mn_ ? fminf(v, o_) : fmaxf(v, o_);                      \
    } while (0)

    {
        const bool w2  = !(lane & 2);
        const bool w4  = !(lane & 4);
        const bool w8  = !(lane & 8);
        const bool w16 = !(lane & 16);
        WSH(1, w2);
        WSH(2, w4);  WSH(1, w4);
        WSH(4, w8);  WSH(2, w8);  WSH(1, w8);
        WSH(8, w16); WSH(4, w16); WSH(2, w16); WSH(1, w16);
        WSH(16, true); WSH(8, true); WSH(4, true); WSH(2, true); WSH(1, true);
    }
#undef WSH

    // ---- Warp-local inclusive scan of sorted run. ----
    float x = v;
#pragma unroll
    for (int off = 1; off < 32; off <<= 1) {
        const float y = __shfl_up_sync(0xffffffffu, x, off);
        if (lane >= off) x += y;
    }

    // Publish run values + run prefix sums.
    srun[wid * 33 + lane]     = v;
    spre[wid * 34 + lane + 1] = x;
    if (lane == 0) spre[wid * 34] = 0.0f;
    __syncthreads();

    // ---- Global rank + global prefix via 7 run-searches. ----
    // rank = lane + sum_{r<wid} cnt_r(<= v) + sum_{r>wid} cnt_r(< v)
    // pre  = x    + sum_{r!=wid} runprefix_r[cnt_r]
    int   rank = lane;
    float pre  = x;
#pragma unroll
    for (int r = 0; r < 8; ++r) {
        if (r == wid) continue;                 // warp-uniform branch
        const int base  = r * 33;
        const int pbase = r * 34;
        int cnt = 0;
        if (r < wid) {
#pragma unroll
            for (int s = 16; s > 0; s >>= 1)
                cnt += (srun[base + cnt + s - 1] <= v) ? s : 0;
            cnt += (srun[base + cnt] <= v) ? 1 : 0;
        } else {
#pragma unroll
            for (int s = 16; s > 0; s >>= 1)
                cnt += (srun[base + cnt + s - 1] < v) ? s : 0;
            cnt += (srun[base + cnt] < v) ? 1 : 0;
        }
        rank += cnt;
        pre  += spre[pbase + cnt];
    }

    const float inv = 1.0f / ((float)N_ELEM * (float)N_ELEM);

    if (diag) {
        float w = v * (float)(2 * rank - 255);
#pragma unroll
        for (int off = 16; off > 0; off >>= 1)
            w += __shfl_xor_sync(0xffffffffu, w, off);
        if (lane == 0) red[wid] = w;
        __syncthreads();
        if (t == 0) {
            float tot = red[0] + red[1] + red[2] + red[3]
                      + red[4] + red[5] + red[6] + red[7];
            atomicAdd(&out[c], tot * inv);
        }
        return;
    }

    // Scatter merged sorted array + prefix (ranks are unique).
    sv[rank]     = v;
    sp[rank + 1] = pre;
    if (t == 0) sp[0] = 0.0f;
    __syncthreads();

    // ---- Closed form queries. ----
    const float k  = spac[c] * 2.0f;
    const float ds = (float)a * k - (float)b * k;   // reference rounding order
    const float c1 = 0.2f * ds;
    const float k1 = p - ds;
    const float k2 = p - c1;

    int cnt1 = 0, cnt2 = 0, cnt3 = 0;
#pragma unroll
    for (int s = 128; s > 0; s >>= 1) {
        cnt1 += (sv[cnt1 + s - 1] <  k1) ? s : 0;
        cnt2 += (sv[cnt2 + s - 1] <= k2) ? s : 0;
        cnt3 += (sv[cnt3 + s - 1] <= p ) ? s : 0;
    }
    cnt1 += (sv[cnt1] <  k1) ? 1 : 0;
    cnt2 += (sv[cnt2] <= k2) ? 1 : 0;
    cnt3 += (sv[cnt3] <= p ) ? 1 : 0;

    const float T = sp[256];
    float contrib = (float)cnt1 * k1 - sp[cnt1]
                  + (T - sp[cnt2]) - (float)(256 - cnt2) * k2
                  - c1 * (float)(256 - cnt3);

#pragma unroll
    for (int off = 16; off > 0; off >>= 1)
        contrib += __shfl_xor_sync(0xffffffffu, contrib, off);
    __syncthreads();
    if (lane == 0) red[wid] = contrib;
    __syncthreads();
    if (t == 0) {
        float tot = red[0] + red[1] + red[2] + red[3]
                  + red[4] + red[5] + red[6] + red[7];
        atomicAdd(&out[c], tot * inv);
    }
}

extern "C" void kernel_launch(void* const* d_in, const int* in_sizes, int n_in,
                              void* d_out, int out_size)
{
    (void)in_sizes; (void)n_in; (void)out_size;
    const float* pred = (const float*)d_in[0];
    const float* spac = (const float*)d_in[1];
    float* out = (float*)d_out;

    cudaMemsetAsync(out, 0, 3 * sizeof(float));
    depthloss_rank<<<408, 256>>>(pred, spac, out);
}